// round 12
// baseline (speedup 1.0000x reference)
#include <cuda_runtime.h>
#include <math.h>

// Problem constants (match reference)
#define N_INPUTSC 2048
#define UNITSC    2048
#define LC        8
#define FANINC    4096
#define TOTALC    18432

#define KC      32            // partial-sum depth (k-chunks of 128 rows)
#define RPC     128           // rows per chunk
#define JT      16            // column tiles of 128
#define CPB     128           // cols per tile
#define GEMV_BLOCKS (KC * JT) // 512
#define MAT_BLOCKS  8         // materialization blocks appended to the grid

// Persistent scratch (allocation-free rule: __device__ globals)
__device__ float g_partial[2][KC * UNITSC];  // ping-pong partials, 256KB each
__device__ float g_outputs[TOTALC];          // materialized state vector

// Sum the KC partials for column u of the previous layer (L2-resident).
__device__ __forceinline__ float sum_partials(const float* __restrict__ P, int u) {
    float s0 = 0.f, s1 = 0.f;
#pragma unroll
    for (int c = 0; c < KC; c += 2) {
        s0 += P[(size_t)c       * UNITSC + u];
        s1 += P[(size_t)(c + 1) * UNITSC + u];
    }
    return s0 + s1;
}

// ---------------------------------------------------------------------------
// fused layer kernel, one launch per layer.
//  - blocks [0, 512): gemv with block-level live-row compaction.
//    Block (kc, jt): rows [kc*128,+128), cols [jt*128,+128).
//    Prologue: 128 threads gather one element each (old slices -> g_outputs;
//    current slice -> recompute from prev partials; future -> dead), then
//    ballot-compact live rows into (srow, sval); tail padded with row 0 /
//    value 0. Main: 8 warps x 16 UNCONDITIONAL iterations — dummy rows hit
//    row 0 (L1) so DRAM traffic is only the live rows (~50% saved overall)
//    while loads stay branch-free and fully pipelined.
//  - blocks [512, 520): materialize slice `layer` into g_outputs.
// ---------------------------------------------------------------------------
__global__ __launch_bounds__(256) void layer_kernel(
    int layer,
    const float* __restrict__ x,
    const int*   __restrict__ node_inds,
    const float* __restrict__ Ws,
    const float* __restrict__ bs)
{
    const int tid  = threadIdx.x;
    const int base = layer << 11;
    const float* Pprev = g_partial[(layer + 1) & 1];
    const float* bprev = bs + (layer - 1) * UNITSC;

    if (blockIdx.x >= GEMV_BLOCKS) {
        // ---- materialize slice `layer` ----
        int u = (blockIdx.x - GEMV_BLOCKS) * 256 + tid;
        float o;
        if (layer == 0) o = x[u];
        else            o = tanhf(sum_partials(Pprev, u) + bprev[u]);
        g_outputs[base + u] = o;
        return;
    }

    const int kc = blockIdx.x >> 4;
    const int jt = blockIdx.x & 15;

    __shared__ float  sval[RPC];
    __shared__ int    srow[RPC];
    __shared__ int    s_wcnt[4];
    __shared__ float4 red[8][32];

    // ---- prologue: gather + compact ----
    float v = 0.f;
    bool  live = false;
    int   pre = 0, wp = tid >> 5;
    if (tid < RPC) {
        srow[tid] = 0;                           // dummy pad: row 0
        sval[tid] = 0.f;                         // dummy pad: value 0
        int idx = node_inds[layer * FANINC + kc * RPC + tid];
        live = (idx < base + UNITSC);
        if (idx < base) {
            v = g_outputs[idx];                  // older slice, materialized
        } else if (live) {
            int u = idx - base;                  // current slice: recompute
            if (layer == 0) v = x[u];
            else            v = tanhf(sum_partials(Pprev, u) + bprev[u]);
        }
        unsigned m = __ballot_sync(0xffffffffu, live);
        pre = __popc(m & ((1u << (tid & 31)) - 1u));
        if ((tid & 31) == 0) s_wcnt[wp] = __popc(m);
    }
    __syncthreads();
    if (tid < RPC && live) {
        int wbase = 0;
#pragma unroll
        for (int w = 0; w < 4; ++w) wbase += (w < wp) ? s_wcnt[w] : 0;
        int p = wbase + pre;
        srow[p] = tid;
        sval[p] = v;
    }
    __syncthreads();

    // ---- main: 8 warps x 16 unconditional row iterations ----
    const int tx = tid & 31;
    const int tg = tid >> 5;
    const float* Wb = Ws + ((size_t)layer * FANINC + kc * RPC) * UNITSC
                    + jt * CPB + tx * 4;

    float ax = 0.f, ay = 0.f, az = 0.f, aw = 0.f;
#pragma unroll
    for (int i = 0; i < 16; ++i) {
        int   r  = tg * 16 + i;
        float gk = sval[r];
        float4 w = *reinterpret_cast<const float4*>(Wb + (size_t)srow[r] * UNITSC);
        ax = fmaf(gk, w.x, ax);
        ay = fmaf(gk, w.y, ay);
        az = fmaf(gk, w.z, az);
        aw = fmaf(gk, w.w, aw);
    }

    red[tg][tx] = make_float4(ax, ay, az, aw);
    __syncthreads();
    if (tg == 0) {
        float4 s = red[0][tx];
#pragma unroll
        for (int r = 1; r < 8; ++r) {
            float4 p = red[r][tx];
            s.x += p.x; s.y += p.y; s.z += p.z; s.w += p.w;
        }
        *reinterpret_cast<float4*>(g_partial[layer & 1]
                                   + kc * UNITSC + jt * CPB + tx * 4) = s;
    }
}

// ---------------------------------------------------------------------------
// final: out = tanh(colsum(layer-7 partials) + b7)
// ---------------------------------------------------------------------------
__global__ __launch_bounds__(256) void final_kernel(
    const float* __restrict__ bs, float* __restrict__ out)
{
    int u = blockIdx.x * 256 + threadIdx.x;
    const float* P = g_partial[(LC - 1) & 1];
    out[u] = tanhf(sum_partials(P, u) + bs[(LC - 1) * UNITSC + u]);
}

extern "C" void kernel_launch(void* const* d_in, const int* in_sizes, int n_in,
                              void* d_out, int out_size) {
    const float* x  = (const float*)d_in[0];   // [2048] f32
    const int*   ni = (const int*)d_in[1];     // [8, 4096] i32
    const float* Ws = (const float*)d_in[2];   // [8, 4096, 2048] f32
    const float* bs = (const float*)d_in[3];   // [8, 2048] f32
    float* out = (float*)d_out;                // [2048] f32

    for (int i = 0; i < LC; ++i) {
        layer_kernel<<<GEMV_BLOCKS + MAT_BLOCKS, 256>>>(i, x, ni, Ws, bs);
    }
    final_kernel<<<UNITSC / 256, 256>>>(bs, out);
}

// round 13
// speedup vs baseline: 1.1280x; 1.1280x over previous
#include <cuda_runtime.h>
#include <math.h>

// Problem constants (match reference)
#define N_INPUTSC 2048
#define UNITSC    2048
#define LC        8
#define FANINC    4096
#define TOTALC    18432

#define KC      32            // partial-sum depth (k-chunks of 128 rows)
#define RPC     128           // rows per chunk
#define JT      16            // column tiles of 128
#define CPB     128           // cols per tile
#define GEMV_BLOCKS (KC * JT) // 512
#define MAT_BLOCKS  8         // materialization blocks appended to the grid

// Persistent scratch (allocation-free rule: __device__ globals)
__device__ float g_partial[2][KC * UNITSC];  // ping-pong partials, 256KB each
__device__ float g_outputs[TOTALC];          // materialized state vector

// Sum the KC partials for column u of the previous layer (L2-resident).
__device__ __forceinline__ float sum_partials(const float* __restrict__ P, int u) {
    float s0 = 0.f, s1 = 0.f;
#pragma unroll
    for (int c = 0; c < KC; c += 2) {
        s0 += P[(size_t)c       * UNITSC + u];
        s1 += P[(size_t)(c + 1) * UNITSC + u];
    }
    return s0 + s1;
}

// Predicated float4 load: issues a single @p ld.global.nc.v4.f32 — no memory
// request when p is false (w stays 0). Straight-line asm so ptxas cannot
// re-roll the batch; all 16 per warp go into flight together.
__device__ __forceinline__ void pred_load4(float4& w, float gk, const float* p) {
    w.x = 0.f; w.y = 0.f; w.z = 0.f; w.w = 0.f;
    asm volatile(
        "{\n\t"
        ".reg .pred lp;\n\t"
        "setp.ne.f32 lp, %4, 0f00000000;\n\t"
        "@lp ld.global.nc.v4.f32 {%0, %1, %2, %3}, [%5];\n\t"
        "}"
        : "+f"(w.x), "+f"(w.y), "+f"(w.z), "+f"(w.w)
        : "f"(gk), "l"(p));
}

// ---------------------------------------------------------------------------
// fused layer kernel, one launch per layer.
//  - blocks [0, 512): gemv. Block (kc, jt): rows [kc*128,+128), cols
//    [jt*128,+128). Prologue: 128 threads gather one element each (old
//    slices -> g_outputs; current slice -> recompute from prev partials;
//    future -> 0). Main: 8 warps x 16 rows; gathered values preloaded to
//    registers, then 16 straight-line predicated LDG.128 (dead rows skip
//    their DRAM traffic but cost no branch), unconditional FMAs.
//  - blocks [512, 520): materialize slice `layer` into g_outputs.
// ---------------------------------------------------------------------------
__global__ __launch_bounds__(256) void layer_kernel(
    int layer,
    const float* __restrict__ x,
    const int*   __restrict__ node_inds,
    const float* __restrict__ Ws,
    const float* __restrict__ bs)
{
    const int tid  = threadIdx.x;
    const int base = layer << 11;
    const float* Pprev = g_partial[(layer + 1) & 1];
    const float* bprev = bs + (layer - 1) * UNITSC;

    if (blockIdx.x >= GEMV_BLOCKS) {
        // ---- materialize slice `layer` ----
        int u = (blockIdx.x - GEMV_BLOCKS) * 256 + tid;
        float o;
        if (layer == 0) o = x[u];
        else            o = tanhf(sum_partials(Pprev, u) + bprev[u]);
        g_outputs[base + u] = o;
        return;
    }

    const int kc = blockIdx.x >> 4;
    const int jt = blockIdx.x & 15;

    __shared__ float  sg[RPC];
    __shared__ float4 red[8][32];

    // Prologue: one gather element per thread (first 128 threads).
    if (tid < RPC) {
        int idx = node_inds[layer * FANINC + kc * RPC + tid];
        float v = 0.f;
        if (idx < base) {
            v = g_outputs[idx];                  // older slice, materialized
        } else if (idx < base + UNITSC) {
            int u = idx - base;                  // current slice: recompute
            if (layer == 0) v = x[u];
            else            v = tanhf(sum_partials(Pprev, u) + bprev[u]);
        }
        sg[tid] = v;
    }
    __syncthreads();

    const int tx = tid & 31;
    const int tg = tid >> 5;                     // warp id: rows tg*16..+15
    const float* Wb = Ws + ((size_t)layer * FANINC + kc * RPC + tg * 16) * UNITSC
                    + jt * CPB + tx * 4;

    // Preload gathered values into registers (breaks LDS out of the chain).
    float gv[16];
#pragma unroll
    for (int i = 0; i < 16; ++i) gv[i] = sg[tg * 16 + i];

    // 16 straight-line predicated loads — all in flight together.
    float4 w[16];
#pragma unroll
    for (int i = 0; i < 16; ++i)
        pred_load4(w[i], gv[i], Wb + (size_t)i * UNITSC);

    float ax = 0.f, ay = 0.f, az = 0.f, aw = 0.f;
#pragma unroll
    for (int i = 0; i < 16; ++i) {
        ax = fmaf(gv[i], w[i].x, ax);
        ay = fmaf(gv[i], w[i].y, ay);
        az = fmaf(gv[i], w[i].z, az);
        aw = fmaf(gv[i], w[i].w, aw);
    }

    red[tg][tx] = make_float4(ax, ay, az, aw);
    __syncthreads();
    if (tg == 0) {
        float4 s = red[0][tx];
#pragma unroll
        for (int r = 1; r < 8; ++r) {
            float4 p = red[r][tx];
            s.x += p.x; s.y += p.y; s.z += p.z; s.w += p.w;
        }
        *reinterpret_cast<float4*>(g_partial[layer & 1]
                                   + kc * UNITSC + jt * CPB + tx * 4) = s;
    }
}

// ---------------------------------------------------------------------------
// final: out = tanh(colsum(layer-7 partials) + b7)
// ---------------------------------------------------------------------------
__global__ __launch_bounds__(256) void final_kernel(
    const float* __restrict__ bs, float* __restrict__ out)
{
    int u = blockIdx.x * 256 + threadIdx.x;
    const float* P = g_partial[(LC - 1) & 1];
    out[u] = tanhf(sum_partials(P, u) + bs[(LC - 1) * UNITSC + u]);
}

extern "C" void kernel_launch(void* const* d_in, const int* in_sizes, int n_in,
                              void* d_out, int out_size) {
    const float* x  = (const float*)d_in[0];   // [2048] f32
    const int*   ni = (const int*)d_in[1];     // [8, 4096] i32
    const float* Ws = (const float*)d_in[2];   // [8, 4096, 2048] f32
    const float* bs = (const float*)d_in[3];   // [8, 2048] f32
    float* out = (float*)d_out;                // [2048] f32

    for (int i = 0; i < LC; ++i) {
        layer_kernel<<<GEMV_BLOCKS + MAT_BLOCKS, 256>>>(i, x, ni, Ws, bs);
    }
    final_kernel<<<UNITSC / 256, 256>>>(bs, out);
}